// round 12
// baseline (speedup 1.0000x reference)
#include <cuda_runtime.h>
#include <cuda_bf16.h>
#include <cstdint>
#include <cstddef>

#define BB 16
#define NN 2048
#define CC 64
#define KK 20
#define OUTC 1024
#define CATC 192
#define NPTS (BB*NN)
#define EPSF 1e-5f

// ---------------- scratch (static __device__, no allocation) ----------------
__device__ float g_D[(size_t)BB*NN*NN];        // 268MB: neg_dist, reused per layer
__device__ int   g_idx[NPTS*KK];
__device__ float g_PQ[(size_t)NPTS*128];       // [P(64) | Q(64)] per point
__device__ float g_hmax[(size_t)NPTS*CC];
__device__ float g_hmin[(size_t)NPTS*CC];
__device__ float g_cat[(size_t)NPTS*CATC];     // f1|f2|f3
__device__ float g_xx[NPTS];
__device__ float g_s1[3][CC];
__device__ float g_s2[3][CC];
__device__ float g_s1f[OUTC];
__device__ float g_s2f[OUTC];
__device__ unsigned g_fmaxe[BB*OUTC];
__device__ unsigned g_fmine[BB*OUTC];
__device__ __nv_bfloat16 g_A2[(size_t)NPTS*576];   // [catH | catH | catL]
__device__ __nv_bfloat16 g_B2[(size_t)OUTC*576];   // [WfH  | WfL  | WfH ]

__device__ __forceinline__ float neg_inf(){ return __int_as_float(0xff800000); }
__device__ __forceinline__ unsigned encf(float f){
  unsigned u = __float_as_uint(f);
  return (u & 0x80000000u) ? ~u : (u | 0x80000000u);
}
__device__ __forceinline__ float decf(unsigned u){
  return __uint_as_float((u & 0x80000000u) ? (u ^ 0x80000000u) : ~u);
}
__device__ __forceinline__ unsigned smem_u32(const void* p){
  return (unsigned)__cvta_generic_to_shared(p);
}

// ---------------- init ----------------
__global__ void k_init(){
  int i = blockIdx.x*256 + threadIdx.x;
  if (i < BB*OUTC){ g_fmaxe[i]=0u; g_fmine[i]=0xFFFFFFFFu; }
  if (i < OUTC){ g_s1f[i]=0.f; g_s2f[i]=0.f; }
  if (i < 3*CC){ (&g_s1[0][0])[i]=0.f; (&g_s2[0][0])[i]=0.f; }
}

// ---------------- squared norms of input x ---------------------------------
__global__ void k_xx0(const float* __restrict__ x){
  int sub = threadIdx.x >> 6;
  int o   = threadIdx.x & 63;
  int p   = blockIdx.x*4 + sub;
  float v = x[(size_t)p*64 + o];
  float s = v*v;
  #pragma unroll
  for (int off=16; off; off>>=1) s += __shfl_down_sync(0xffffffffu, s, off);
  __shared__ float sm[8];
  if ((threadIdx.x & 31)==0) sm[threadIdx.x>>5] = s;
  __syncthreads();
  if (o==0) g_xx[p] = sm[sub*2] + sm[sub*2+1];
}

// ------- symmetric neg_dist GEMM (fp32), triangular grid, 3 CTAs/SM ---------
__global__ void __launch_bounds__(256, 3) k_dist(const float* __restrict__ xext,
                                                 int useCat, int catOff, int ldf){
  // decode triangular tile index: blockIdx.x in [0,136)
  int rem = blockIdx.x, cy = 0;
  while (rem >= 16 - cy){ rem -= 16 - cy; cy++; }
  int cx = cy + rem;
  __shared__ float As[32][136];   // [k][m]
  __shared__ float Bs[32][136];   // [k][n]
  const float* feat = useCat ? (g_cat + catOff) : xext;
  int b = blockIdx.z;
  int rb = cy*128, cb = cx*128;
  const float* Fb = feat + (size_t)b*NN*ldf;
  int t = threadIdx.x;
  int ty = t>>4, tx = t&15;
  int m0 = ty*8, n0 = tx*8;
  float acc[8][8] = {};
  for (int kc=0; kc<2; kc++){
    __syncthreads();
    #pragma unroll
    for (int i=0;i<4;i++){
      int j = t + i*256;
      int m = j>>3, k4 = (j&7)*4;
      float4 a = *(const float4*)(Fb + (size_t)(rb+m)*ldf + kc*32 + k4);
      As[k4+0][m]=a.x; As[k4+1][m]=a.y; As[k4+2][m]=a.z; As[k4+3][m]=a.w;
      float4 c = *(const float4*)(Fb + (size_t)(cb+m)*ldf + kc*32 + k4);
      Bs[k4+0][m]=c.x; Bs[k4+1][m]=c.y; Bs[k4+2][m]=c.z; Bs[k4+3][m]=c.w;
    }
    __syncthreads();
    #pragma unroll 8
    for (int k=0;k<32;k++){
      float av[8], bv[8];
      *(float4*)&av[0] = *(const float4*)&As[k][m0];
      *(float4*)&av[4] = *(const float4*)&As[k][m0+4];
      *(float4*)&bv[0] = *(const float4*)&Bs[k][n0];
      *(float4*)&bv[4] = *(const float4*)&Bs[k][n0+4];
      #pragma unroll
      for (int i=0;i<8;i++)
        #pragma unroll
        for (int j2=0;j2<8;j2++)
          acc[i][j2] += av[i]*bv[j2];
    }
  }
  int grow = b*NN + rb + m0;
  int gcol = b*NN + cb + n0;
  float xr[8], xc[8];
  #pragma unroll
  for (int i=0;i<8;i++)  xr[i]=g_xx[grow+i];
  #pragma unroll
  for (int j2=0;j2<8;j2++) xc[j2]=g_xx[gcol+j2];
  float d[8][8];
  #pragma unroll
  for (int i=0;i<8;i++)
    #pragma unroll
    for (int j2=0;j2<8;j2++)
      d[i][j2] = 2.f*acc[i][j2]-xr[i]-xc[j2];
  #pragma unroll
  for (int i=0;i<8;i++){
    float* dst = &g_D[(size_t)(grow+i)*NN + cb + n0];
    *(float4*)dst     = *(float4*)&d[i][0];
    *(float4*)(dst+4) = *(float4*)&d[i][4];
  }
  if (cb > rb){
    #pragma unroll
    for (int j2=0;j2<8;j2++){
      float4 w1, w2;
      w1.x=d[0][j2]; w1.y=d[1][j2]; w1.z=d[2][j2]; w1.w=d[3][j2];
      w2.x=d[4][j2]; w2.y=d[5][j2]; w2.z=d[6][j2]; w2.w=d[7][j2];
      float* dst = &g_D[(size_t)(gcol+j2)*NN + rb + m0];
      *(float4*)dst     = w1;
      *(float4*)(dst+4) = w2;
    }
  }
}

// ------- top-20 per row: float-pruned scan + packed u64 warp insertion ------
__global__ void __launch_bounds__(256) k_topk(){
  int w = threadIdx.x>>5, lane = threadIdx.x&31;
  int row = blockIdx.x*8 + w;
  const float4* drow4 = (const float4*)(g_D + (size_t)row*NN);

  unsigned long long rk  = 0x007fffff80000000ull;  // key(-inf, INT_MAX)
  unsigned long long thr = 0x007fffff80000000ull;
  float vthr = neg_inf();

  for (int b=0; b<16; b++){
    int e = b*32 + lane;
    float4 dv = __ldg(&drow4[e]);
    float bmax = fmaxf(fmaxf(dv.x, dv.y), fmaxf(dv.z, dv.w));
    if (!__ballot_sync(0xffffffffu, bmax >= vthr)) continue;

    int i0 = e*4;
    unsigned long long keys[4];
    keys[0] = ((unsigned long long)encf(dv.x) << 32) | (unsigned)(~(i0+0));
    keys[1] = ((unsigned long long)encf(dv.y) << 32) | (unsigned)(~(i0+1));
    keys[2] = ((unsigned long long)encf(dv.z) << 32) | (unsigned)(~(i0+2));
    keys[3] = ((unsigned long long)encf(dv.w) << 32) | (unsigned)(~(i0+3));
    #pragma unroll
    for (int q=0;q<4;q++){
      unsigned long long key = keys[q];
      unsigned m = __ballot_sync(0xffffffffu, key > thr);
      while (m){
        int src = __ffs(m) - 1;
        unsigned long long ck = __shfl_sync(0xffffffffu, key, src);
        unsigned bet = __ballot_sync(0xffffffffu, rk > ck);
        int pos = __popc(bet);
        unsigned long long prev = __shfl_up_sync(0xffffffffu, rk, 1);
        if (lane == pos)      rk = ck;
        else if (lane > pos)  rk = prev;
        thr = __shfl_sync(0xffffffffu, rk, 19);
        if (lane == src) key = 0ull;
        m = __ballot_sync(0xffffffffu, key > thr);
      }
    }
    vthr = decf((unsigned)(thr >> 32));
  }
  if (lane < KK) g_idx[row*KK + lane] = (int)(~(unsigned)(rk & 0xffffffffu));
}

// ---------------- P/Q projection -------------------------------------------
__global__ void __launch_bounds__(256) k_pq(const float* __restrict__ xext,
                                            int useCat, int catOff, int ldf,
                                            const float* __restrict__ W){
  const float* feat = useCat ? (g_cat + catOff) : xext;
  __shared__ float Fs[64][64];    // [m][k]
  __shared__ float Ws[64][128];   // [k][j]
  int t = threadIdx.x;
  int mb = blockIdx.x*64;
  #pragma unroll
  for (int i=0;i<4;i++){
    int j = t + i*256;
    int m = j>>4, k4=(j&15)*4;
    float4 a = *(const float4*)(feat + (size_t)(mb+m)*ldf + k4);
    *(float4*)&Fs[m][k4] = a;
  }
  #pragma unroll
  for (int i=0;i<32;i++){
    int l = t + i*256;
    int k = l>>7, j = l&127;
    Ws[k][j] = (j<64)? W[j*128 + k] : W[(j-64)*128 + 64 + k];
  }
  __syncthreads();
  int ty=t>>4, tx=t&15;
  int m0=ty*4, o0=tx*8;
  float acc[4][8] = {};
  #pragma unroll 8
  for (int k=0;k<64;k++){
    float av[4];
    #pragma unroll
    for (int i=0;i<4;i++) av[i]=Fs[m0+i][k];
    float4 w0=*(const float4*)&Ws[k][o0];
    float4 w1=*(const float4*)&Ws[k][o0+4];
    float wv[8]={w0.x,w0.y,w0.z,w0.w,w1.x,w1.y,w1.z,w1.w};
    #pragma unroll
    for (int i=0;i<4;i++)
      #pragma unroll
      for (int j2=0;j2<8;j2++)
        acc[i][j2] += av[i]*wv[j2];
  }
  #pragma unroll
  for (int i=0;i<4;i++){
    float* dst = g_PQ + (size_t)(mb+m0+i)*128 + o0;
    float4 u,vv;
    u.x=acc[i][0]; u.y=acc[i][1]; u.z=acc[i][2]; u.w=acc[i][3];
    vv.x=acc[i][4]; vv.y=acc[i][5]; vv.z=acc[i][6]; vv.w=acc[i][7];
    *(float4*)dst = u;
    *(float4*)(dst+4) = vv;
  }
}

// -------- gather: h = P[m] + (Q[n]-P[n]); max/min over k + channel stats ----
__global__ void __launch_bounds__(256) k_gather(int layer){
  __shared__ float ss1[64], ss2[64];
  int t = threadIdx.x;
  if (t<64){ ss1[t]=0.f; ss2[t]=0.f; }
  __syncthreads();
  int w=t>>5, lane=t&31;
  float ls1a=0.f, ls1b=0.f, ls2a=0.f, ls2b=0.f;
  for (int p=0;p<8;p++){
    int point = blockIdx.x*64 + w*8 + p;
    int b = point >> 11;
    const float* pqn = g_PQ + (size_t)point*128;
    float ra  = pqn[64+lane] - pqn[lane];
    float rb2 = pqn[96+lane] - pqn[32+lane];
    float hxa=neg_inf(), hxb=neg_inf();
    float hna=-neg_inf(), hnb=-neg_inf();
    const int* ids = g_idx + point*KK;
    #pragma unroll
    for (int k=0;k<KK;k++){
      int m = ids[k];
      const float* pm = g_PQ + (size_t)((b<<11)+m)*128;
      float ha = pm[lane]    + ra;
      float hb = pm[32+lane] + rb2;
      ls1a+=ha; ls2a+=ha*ha; hxa=fmaxf(hxa,ha); hna=fminf(hna,ha);
      ls1b+=hb; ls2b+=hb*hb; hxb=fmaxf(hxb,hb); hnb=fminf(hnb,hb);
    }
    g_hmax[(size_t)point*64+lane]=hxa; g_hmax[(size_t)point*64+32+lane]=hxb;
    g_hmin[(size_t)point*64+lane]=hna; g_hmin[(size_t)point*64+32+lane]=hnb;
  }
  atomicAdd(&ss1[lane],    ls1a); atomicAdd(&ss1[lane+32], ls1b);
  atomicAdd(&ss2[lane],    ls2a); atomicAdd(&ss2[lane+32], ls2b);
  __syncthreads();
  if (t<64){ atomicAdd(&g_s1[layer][t], ss1[t]); atomicAdd(&g_s2[layer][t], ss2[t]); }
}

// -------- finalize edge layer: BN+lrelu -> cat, xx, bf16-split for fgemm ----
__global__ void k_efinal(int layer, const float* __restrict__ gg,
                         const float* __restrict__ bbv, int catOff){
  int sub = threadIdx.x>>6;
  int o   = threadIdx.x & 63;
  int p   = blockIdx.x*4 + sub;
  const float cnt = (float)NPTS * (float)KK;
  float mean = g_s1[layer][o]/cnt;
  float var  = g_s2[layer][o]/cnt - mean*mean;
  float scale = rsqrtf(var + EPSF) * gg[o];
  float shift = bbv[o] - mean*scale;
  float h = (scale>=0.f)? g_hmax[(size_t)p*64+o] : g_hmin[(size_t)p*64+o];
  float y = h*scale + shift;
  y = (y>=0.f)? y : 0.2f*y;
  g_cat[(size_t)p*CATC + catOff + o] = y;
  // fused split-bf16 write for the final tensor GEMM
  __nv_bfloat16 hb = __float2bfloat16(y);
  __nv_bfloat16 lb = __float2bfloat16(y - __bfloat162float(hb));
  size_t ab = (size_t)p*576 + catOff + o;
  g_A2[ab]       = hb;
  g_A2[ab + 192] = hb;
  g_A2[ab + 384] = lb;
  float s = y*y;
  #pragma unroll
  for (int off=16; off; off>>=1) s += __shfl_down_sync(0xffffffffu, s, off);
  __shared__ float sm[8];
  if ((threadIdx.x&31)==0) sm[threadIdx.x>>5]=s;
  __syncthreads();
  if (o==0) g_xx[p] = sm[sub*2]+sm[sub*2+1];
}

// -------- bf16 split conversion of Wf ---------------------------------------
__global__ void k_cvtB(const float* __restrict__ Wf){
  int idx = blockIdx.x*256 + threadIdx.x;      // OUTC*CATC
  int o = idx / CATC, c = idx - o*CATC;
  float x = Wf[(size_t)o*CATC + c];
  __nv_bfloat16 h = __float2bfloat16(x);
  __nv_bfloat16 lo = __float2bfloat16(x - __bfloat162float(h));
  size_t base = (size_t)o*576;
  g_B2[base + c]       = h;
  g_B2[base + 192 + c] = lo;
  g_B2[base + 384 + c] = h;
}

// -------- final GEMM via mma.sync bf16 (K=576 split), fused stats epilogue --
__global__ void __launch_bounds__(256) k_fgemm(){
  __shared__ __nv_bfloat16 sA[128][40];
  __shared__ __nv_bfloat16 sB[128][40];
  __shared__ float rmx[2][128], rmn[2][128], rs[2][128], rq[2][128];
  int t = threadIdx.x, lane = t&31, wid = t>>5;
  int wm = wid>>2, wn = wid&3;
  int rb = blockIdx.x*128, ob = blockIdx.y*128;
  int b = rb>>11;
  float acc[4][4][4];
  #pragma unroll
  for (int i=0;i<4;i++)
    #pragma unroll
    for (int j=0;j<4;j++)
      #pragma unroll
      for (int e=0;e<4;e++) acc[i][j][e]=0.f;

  for (int kc=0; kc<18; kc++){
    __syncthreads();
    #pragma unroll
    for (int i=0;i<2;i++){
      int s = t*2 + i;                 // 0..511
      int row = s>>2, seg = (s&3)*8;
      *(uint4*)&sA[row][seg] = *(const uint4*)&g_A2[(size_t)(rb+row)*576 + kc*32 + seg];
      *(uint4*)&sB[row][seg] = *(const uint4*)&g_B2[(size_t)(ob+row)*576 + kc*32 + seg];
    }
    __syncthreads();
    #pragma unroll
    for (int ks=0; ks<2; ks++){
      unsigned af[4][4];
      #pragma unroll
      for (int i=0;i<4;i++){
        int row = wm*64 + i*16 + (lane & 15);
        int col = ks*16 + (lane>>4)*8;
        unsigned addr = smem_u32(&sA[row][col]);
        asm volatile("ldmatrix.sync.aligned.m8n8.x4.shared.b16 {%0,%1,%2,%3}, [%4];"
          : "=r"(af[i][0]),"=r"(af[i][1]),"=r"(af[i][2]),"=r"(af[i][3]) : "r"(addr));
      }
      unsigned bfm[4][2];
      #pragma unroll
      for (int j=0;j<4;j++){
        int l16 = lane & 15;
        int row = wn*32 + j*8 + (l16 & 7);
        int col = ks*16 + (l16>>3)*8;
        unsigned addr = smem_u32(&sB[row][col]);
        asm volatile("ldmatrix.sync.aligned.m8n8.x2.shared.b16 {%0,%1}, [%2];"
          : "=r"(bfm[j][0]),"=r"(bfm[j][1]) : "r"(addr));
      }
      #pragma unroll
      for (int i=0;i<4;i++)
        #pragma unroll
        for (int j=0;j<4;j++){
          asm volatile(
            "mma.sync.aligned.m16n8k16.row.col.f32.bf16.bf16.f32 "
            "{%0,%1,%2,%3}, {%4,%5,%6,%7}, {%8,%9}, {%0,%1,%2,%3};"
            : "+f"(acc[i][j][0]),"+f"(acc[i][j][1]),"+f"(acc[i][j][2]),"+f"(acc[i][j][3])
            : "r"(af[i][0]),"r"(af[i][1]),"r"(af[i][2]),"r"(af[i][3]),
              "r"(bfm[j][0]),"r"(bfm[j][1]));
        }
    }
  }
  // ---- fused stats epilogue ----
  #pragma unroll
  for (int j=0;j<4;j++){
    #pragma unroll
    for (int e=0;e<2;e++){
      float v0 = acc[0][j][e], v1 = acc[0][j][e+2];
      float mx = fmaxf(v0,v1), mn = fminf(v0,v1);
      float s = v0+v1, q = v0*v0+v1*v1;
      #pragma unroll
      for (int i=1;i<4;i++){
        v0 = acc[i][j][e]; v1 = acc[i][j][e+2];
        mx = fmaxf(mx, fmaxf(v0,v1));
        mn = fminf(mn, fminf(v0,v1));
        s += v0+v1; q += v0*v0+v1*v1;
      }
      #pragma unroll
      for (int off=4; off<32; off<<=1){
        mx = fmaxf(mx, __shfl_xor_sync(0xffffffffu, mx, off));
        mn = fminf(mn, __shfl_xor_sync(0xffffffffu, mn, off));
        s += __shfl_xor_sync(0xffffffffu, s, off);
        q += __shfl_xor_sync(0xffffffffu, q, off);
      }
      if (lane < 4){
        int col = wn*32 + j*8 + lane*2 + e;
        rmx[wm][col]=mx; rmn[wm][col]=mn; rs[wm][col]=s; rq[wm][col]=q;
      }
    }
  }
  __syncthreads();
  if (t < 128){
    float mx = fmaxf(rmx[0][t], rmx[1][t]);
    float mn = fminf(rmn[0][t], rmn[1][t]);
    float s  = rs[0][t] + rs[1][t];
    float q  = rq[0][t] + rq[1][t];
    atomicMax(&g_fmaxe[b*OUTC + ob + t], encf(mx));
    atomicMin(&g_fmine[b*OUTC + ob + t], encf(mn));
    atomicAdd(&g_s1f[ob + t], s);
    atomicAdd(&g_s2f[ob + t], q);
  }
}

// -------- final BN + lrelu + pick max/min ----------------------------------
__global__ void k_fout(const float* __restrict__ gf, const float* __restrict__ bf,
                       float* __restrict__ out){
  int i = blockIdx.x*256 + threadIdx.x;   // 0..16383
  int o = i & (OUTC-1);
  const float cnt = (float)NPTS;
  float mean = g_s1f[o]/cnt;
  float var  = g_s2f[o]/cnt - mean*mean;
  float scale = rsqrtf(var + EPSF) * gf[o];
  float shift = bf[o] - mean*scale;
  float h = (scale>=0.f)? decf(g_fmaxe[i]) : decf(g_fmine[i]);
  float y = h*scale + shift;
  out[i] = (y>=0.f)? y : 0.2f*y;
}

extern "C" void kernel_launch(void* const* d_in, const int* in_sizes, int n_in,
                              void* d_out, int out_size){
  const float* x   = (const float*)d_in[0];
  const float* W[3]  = {(const float*)d_in[1],(const float*)d_in[4],(const float*)d_in[7]};
  const float* G[3]  = {(const float*)d_in[2],(const float*)d_in[5],(const float*)d_in[8]};
  const float* Bv[3] = {(const float*)d_in[3],(const float*)d_in[6],(const float*)d_in[9]};
  const float* Wf = (const float*)d_in[10];
  const float* gf = (const float*)d_in[11];
  const float* bf = (const float*)d_in[12];
  float* out = (float*)d_out;

  k_init<<<64,256>>>();
  k_xx0<<<NPTS/4,256>>>(x);
  k_cvtB<<<(OUTC*CATC)/256,256>>>(Wf);
  for (int l=0;l<3;l++){
    int useCat = (l>0);
    int catOff = useCat ? (l-1)*64 : 0;
    int ldf    = useCat ? CATC : CC;
    k_dist <<<dim3(136, 1, BB),256>>>(x, useCat, catOff, ldf);
    k_topk <<<NPTS/8,256>>>();
    k_pq   <<<NPTS/64,256>>>(x, useCat, catOff, ldf, W[l]);
    k_gather<<<NPTS/64,256>>>(l);
    k_efinal<<<NPTS/4,256>>>(l, G[l], Bv[l], l*64);
  }
  k_fgemm<<<dim3(NPTS/128, OUTC/128),256>>>();
  k_fout <<<BB*OUTC/256,256>>>(gf, bf, out);
}

// round 13
// speedup vs baseline: 1.3053x; 1.3053x over previous
#include <cuda_runtime.h>
#include <cuda_bf16.h>
#include <cstdint>
#include <cstddef>

#define BB 16
#define NN 2048
#define CC 64
#define KK 20
#define OUTC 1024
#define CATC 192
#define NPTS (BB*NN)
#define EPSF 1e-5f

// ---------------- scratch (static __device__, no allocation) ----------------
__device__ float g_D[(size_t)BB*NN*NN];        // 268MB: neg_dist, reused per layer
__device__ int   g_idx[NPTS*KK];
__device__ float g_PQ[(size_t)NPTS*128];       // [P(64) | Q(64)] per point
__device__ float g_hmax[(size_t)NPTS*CC];
__device__ float g_hmin[(size_t)NPTS*CC];
__device__ float g_cat[(size_t)NPTS*CATC];     // f1|f2|f3
__device__ float g_xx[NPTS];
__device__ float g_s1[3][CC];
__device__ float g_s2[3][CC];
__device__ float g_s1f[OUTC];
__device__ float g_s2f[OUTC];
__device__ unsigned g_fmaxe[BB*OUTC];
__device__ unsigned g_fmine[BB*OUTC];
__device__ __nv_bfloat16 g_A2[(size_t)NPTS*576];   // [catH | catH | catL]
__device__ __nv_bfloat16 g_B2[(size_t)OUTC*576];   // [WfH  | WfL  | WfH ]

__device__ __forceinline__ float neg_inf(){ return __int_as_float(0xff800000); }
__device__ __forceinline__ unsigned encf(float f){
  unsigned u = __float_as_uint(f);
  return (u & 0x80000000u) ? ~u : (u | 0x80000000u);
}
__device__ __forceinline__ float decf(unsigned u){
  return __uint_as_float((u & 0x80000000u) ? (u ^ 0x80000000u) : ~u);
}
__device__ __forceinline__ unsigned smem_u32(const void* p){
  return (unsigned)__cvta_generic_to_shared(p);
}

// ---------------- init ----------------
__global__ void k_init(){
  int i = blockIdx.x*256 + threadIdx.x;
  if (i < BB*OUTC){ g_fmaxe[i]=0u; g_fmine[i]=0xFFFFFFFFu; }
  if (i < OUTC){ g_s1f[i]=0.f; g_s2f[i]=0.f; }
  if (i < 3*CC){ (&g_s1[0][0])[i]=0.f; (&g_s2[0][0])[i]=0.f; }
}

// ---------------- squared norms of input x ---------------------------------
__global__ void k_xx0(const float* __restrict__ x){
  int sub = threadIdx.x >> 6;
  int o   = threadIdx.x & 63;
  int p   = blockIdx.x*4 + sub;
  float v = x[(size_t)p*64 + o];
  float s = v*v;
  #pragma unroll
  for (int off=16; off; off>>=1) s += __shfl_down_sync(0xffffffffu, s, off);
  __shared__ float sm[8];
  if ((threadIdx.x & 31)==0) sm[threadIdx.x>>5] = s;
  __syncthreads();
  if (o==0) g_xx[p] = sm[sub*2] + sm[sub*2+1];
}

// ------- symmetric neg_dist GEMM (fp32), triangular grid --------------------
__global__ void __launch_bounds__(256) k_dist(const float* __restrict__ xext,
                                              int useCat, int catOff, int ldf){
  // decode triangular tile index: blockIdx.x in [0,136)
  int rem = blockIdx.x, cy = 0;
  while (rem >= 16 - cy){ rem -= 16 - cy; cy++; }
  int cx = cy + rem;
  __shared__ float As[32][136];   // [k][m]
  __shared__ float Bs[32][136];   // [k][n]
  const float* feat = useCat ? (g_cat + catOff) : xext;
  int b = blockIdx.z;
  int rb = cy*128, cb = cx*128;
  const float* Fb = feat + (size_t)b*NN*ldf;
  int t = threadIdx.x;
  int ty = t>>4, tx = t&15;
  int m0 = ty*8, n0 = tx*8;
  float acc[8][8] = {};
  for (int kc=0; kc<2; kc++){
    __syncthreads();
    #pragma unroll
    for (int i=0;i<4;i++){
      int j = t + i*256;
      int m = j>>3, k4 = (j&7)*4;
      float4 a = *(const float4*)(Fb + (size_t)(rb+m)*ldf + kc*32 + k4);
      As[k4+0][m]=a.x; As[k4+1][m]=a.y; As[k4+2][m]=a.z; As[k4+3][m]=a.w;
      float4 c = *(const float4*)(Fb + (size_t)(cb+m)*ldf + kc*32 + k4);
      Bs[k4+0][m]=c.x; Bs[k4+1][m]=c.y; Bs[k4+2][m]=c.z; Bs[k4+3][m]=c.w;
    }
    __syncthreads();
    #pragma unroll 8
    for (int k=0;k<32;k++){
      float av[8], bv[8];
      *(float4*)&av[0] = *(const float4*)&As[k][m0];
      *(float4*)&av[4] = *(const float4*)&As[k][m0+4];
      *(float4*)&bv[0] = *(const float4*)&Bs[k][n0];
      *(float4*)&bv[4] = *(const float4*)&Bs[k][n0+4];
      #pragma unroll
      for (int i=0;i<8;i++)
        #pragma unroll
        for (int j2=0;j2<8;j2++)
          acc[i][j2] += av[i]*bv[j2];
    }
  }
  int grow = b*NN + rb + m0;
  int gcol = b*NN + cb + n0;
  float xr[8], xc[8];
  #pragma unroll
  for (int i=0;i<8;i++)  xr[i]=g_xx[grow+i];
  #pragma unroll
  for (int j2=0;j2<8;j2++) xc[j2]=g_xx[gcol+j2];
  float d[8][8];
  #pragma unroll
  for (int i=0;i<8;i++)
    #pragma unroll
    for (int j2=0;j2<8;j2++)
      d[i][j2] = 2.f*acc[i][j2]-xr[i]-xc[j2];
  #pragma unroll
  for (int i=0;i<8;i++){
    float* dst = &g_D[(size_t)(grow+i)*NN + cb + n0];
    *(float4*)dst     = *(float4*)&d[i][0];
    *(float4*)(dst+4) = *(float4*)&d[i][4];
  }
  if (cb > rb){
    #pragma unroll
    for (int j2=0;j2<8;j2++){
      float4 w1, w2;
      w1.x=d[0][j2]; w1.y=d[1][j2]; w1.z=d[2][j2]; w1.w=d[3][j2];
      w2.x=d[4][j2]; w2.y=d[5][j2]; w2.z=d[6][j2]; w2.w=d[7][j2];
      float* dst = &g_D[(size_t)(gcol+j2)*NN + rb + m0];
      *(float4*)dst     = w1;
      *(float4*)(dst+4) = w2;
    }
  }
}

// ------- top-20 per row: prefetched float-pruned scan + u64 warp insertion --
__global__ void __launch_bounds__(256) k_topk(){
  int w = threadIdx.x>>5, lane = threadIdx.x&31;
  int row = blockIdx.x*8 + w;
  const float4* drow4 = (const float4*)(g_D + (size_t)row*NN);

  unsigned long long rk  = 0x007fffff80000000ull;  // key(-inf, INT_MAX)
  unsigned long long thr = 0x007fffff80000000ull;
  float vthr = neg_inf();

  float4 dv = __ldg(&drow4[lane]);
  for (int b=0; b<16; b++){
    // prefetch next batch while processing this one
    float4 nxt;
    if (b < 15) nxt = __ldg(&drow4[(b+1)*32 + lane]);
    float bmax = fmaxf(fmaxf(dv.x, dv.y), fmaxf(dv.z, dv.w));
    if (__ballot_sync(0xffffffffu, bmax >= vthr)){
      int i0 = (b*32 + lane)*4;
      unsigned long long keys[4];
      keys[0] = ((unsigned long long)encf(dv.x) << 32) | (unsigned)(~(i0+0));
      keys[1] = ((unsigned long long)encf(dv.y) << 32) | (unsigned)(~(i0+1));
      keys[2] = ((unsigned long long)encf(dv.z) << 32) | (unsigned)(~(i0+2));
      keys[3] = ((unsigned long long)encf(dv.w) << 32) | (unsigned)(~(i0+3));
      #pragma unroll
      for (int q=0;q<4;q++){
        unsigned long long key = keys[q];
        unsigned m = __ballot_sync(0xffffffffu, key > thr);
        while (m){
          int src = __ffs(m) - 1;
          unsigned long long ck = __shfl_sync(0xffffffffu, key, src);
          unsigned bet = __ballot_sync(0xffffffffu, rk > ck);
          int pos = __popc(bet);
          unsigned long long prev = __shfl_up_sync(0xffffffffu, rk, 1);
          if (lane == pos)      rk = ck;
          else if (lane > pos)  rk = prev;
          thr = __shfl_sync(0xffffffffu, rk, 19);
          if (lane == src) key = 0ull;
          m = __ballot_sync(0xffffffffu, key > thr);
        }
      }
      vthr = decf((unsigned)(thr >> 32));
    }
    dv = nxt;
  }
  if (lane < KK) g_idx[row*KK + lane] = (int)(~(unsigned)(rk & 0xffffffffu));
}

// ---------------- P/Q projection -------------------------------------------
__global__ void __launch_bounds__(256) k_pq(const float* __restrict__ xext,
                                            int useCat, int catOff, int ldf,
                                            const float* __restrict__ W){
  const float* feat = useCat ? (g_cat + catOff) : xext;
  __shared__ float Fs[64][64];    // [m][k]
  __shared__ float Ws[64][128];   // [k][j]
  int t = threadIdx.x;
  int mb = blockIdx.x*64;
  #pragma unroll
  for (int i=0;i<4;i++){
    int j = t + i*256;
    int m = j>>4, k4=(j&15)*4;
    float4 a = *(const float4*)(feat + (size_t)(mb+m)*ldf + k4);
    *(float4*)&Fs[m][k4] = a;
  }
  #pragma unroll
  for (int i=0;i<32;i++){
    int l = t + i*256;
    int k = l>>7, j = l&127;
    Ws[k][j] = (j<64)? W[j*128 + k] : W[(j-64)*128 + 64 + k];
  }
  __syncthreads();
  int ty=t>>4, tx=t&15;
  int m0=ty*4, o0=tx*8;
  float acc[4][8] = {};
  #pragma unroll 8
  for (int k=0;k<64;k++){
    float av[4];
    #pragma unroll
    for (int i=0;i<4;i++) av[i]=Fs[m0+i][k];
    float4 w0=*(const float4*)&Ws[k][o0];
    float4 w1=*(const float4*)&Ws[k][o0+4];
    float wv[8]={w0.x,w0.y,w0.z,w0.w,w1.x,w1.y,w1.z,w1.w};
    #pragma unroll
    for (int i=0;i<4;i++)
      #pragma unroll
      for (int j2=0;j2<8;j2++)
        acc[i][j2] += av[i]*wv[j2];
  }
  #pragma unroll
  for (int i=0;i<4;i++){
    float* dst = g_PQ + (size_t)(mb+m0+i)*128 + o0;
    float4 u,vv;
    u.x=acc[i][0]; u.y=acc[i][1]; u.z=acc[i][2]; u.w=acc[i][3];
    vv.x=acc[i][4]; vv.y=acc[i][5]; vv.z=acc[i][6]; vv.w=acc[i][7];
    *(float4*)dst = u;
    *(float4*)(dst+4) = vv;
  }
}

// -------- gather: h = P[m] + (Q[n]-P[n]); max/min over k + channel stats ----
__global__ void __launch_bounds__(256) k_gather(int layer){
  __shared__ float ss1[64], ss2[64];
  int t = threadIdx.x;
  if (t<64){ ss1[t]=0.f; ss2[t]=0.f; }
  __syncthreads();
  int w=t>>5, lane=t&31;
  float ls1a=0.f, ls1b=0.f, ls2a=0.f, ls2b=0.f;
  for (int p=0;p<8;p++){
    int point = blockIdx.x*64 + w*8 + p;
    int b = point >> 11;
    const float* pqn = g_PQ + (size_t)point*128;
    float ra  = pqn[64+lane] - pqn[lane];
    float rb2 = pqn[96+lane] - pqn[32+lane];
    float hxa=neg_inf(), hxb=neg_inf();
    float hna=-neg_inf(), hnb=-neg_inf();
    const int* ids = g_idx + point*KK;
    #pragma unroll
    for (int k=0;k<KK;k++){
      int m = ids[k];
      const float* pm = g_PQ + (size_t)((b<<11)+m)*128;
      float ha = pm[lane]    + ra;
      float hb = pm[32+lane] + rb2;
      ls1a+=ha; ls2a+=ha*ha; hxa=fmaxf(hxa,ha); hna=fminf(hna,ha);
      ls1b+=hb; ls2b+=hb*hb; hxb=fmaxf(hxb,hb); hnb=fminf(hnb,hb);
    }
    g_hmax[(size_t)point*64+lane]=hxa; g_hmax[(size_t)point*64+32+lane]=hxb;
    g_hmin[(size_t)point*64+lane]=hna; g_hmin[(size_t)point*64+32+lane]=hnb;
  }
  atomicAdd(&ss1[lane],    ls1a); atomicAdd(&ss1[lane+32], ls1b);
  atomicAdd(&ss2[lane],    ls2a); atomicAdd(&ss2[lane+32], ls2b);
  __syncthreads();
  if (t<64){ atomicAdd(&g_s1[layer][t], ss1[t]); atomicAdd(&g_s2[layer][t], ss2[t]); }
}

// -------- finalize edge layer: BN+lrelu -> cat, xx, bf16-split for fgemm ----
__global__ void k_efinal(int layer, const float* __restrict__ gg,
                         const float* __restrict__ bbv, int catOff){
  int sub = threadIdx.x>>6;
  int o   = threadIdx.x & 63;
  int p   = blockIdx.x*4 + sub;
  const float cnt = (float)NPTS * (float)KK;
  float mean = g_s1[layer][o]/cnt;
  float var  = g_s2[layer][o]/cnt - mean*mean;
  float scale = rsqrtf(var + EPSF) * gg[o];
  float shift = bbv[o] - mean*scale;
  float h = (scale>=0.f)? g_hmax[(size_t)p*64+o] : g_hmin[(size_t)p*64+o];
  float y = h*scale + shift;
  y = (y>=0.f)? y : 0.2f*y;
  g_cat[(size_t)p*CATC + catOff + o] = y;
  // fused split-bf16 write for the final tensor GEMM
  __nv_bfloat16 hb = __float2bfloat16(y);
  __nv_bfloat16 lb = __float2bfloat16(y - __bfloat162float(hb));
  size_t ab = (size_t)p*576 + catOff + o;
  g_A2[ab]       = hb;
  g_A2[ab + 192] = hb;
  g_A2[ab + 384] = lb;
  float s = y*y;
  #pragma unroll
  for (int off=16; off; off>>=1) s += __shfl_down_sync(0xffffffffu, s, off);
  __shared__ float sm[8];
  if ((threadIdx.x&31)==0) sm[threadIdx.x>>5]=s;
  __syncthreads();
  if (o==0) g_xx[p] = sm[sub*2]+sm[sub*2+1];
}

// -------- bf16 split conversion of Wf ---------------------------------------
__global__ void k_cvtB(const float* __restrict__ Wf){
  int idx = blockIdx.x*256 + threadIdx.x;      // OUTC*CATC
  int o = idx / CATC, c = idx - o*CATC;
  float x = Wf[(size_t)o*CATC + c];
  __nv_bfloat16 h = __float2bfloat16(x);
  __nv_bfloat16 lo = __float2bfloat16(x - __bfloat162float(h));
  size_t base = (size_t)o*576;
  g_B2[base + c]       = h;
  g_B2[base + 192 + c] = lo;
  g_B2[base + 384 + c] = h;
}

// -------- final GEMM via mma.sync bf16 (K=576 split), double-buffered -------
__global__ void __launch_bounds__(256) k_fgemm(){
  __shared__ __nv_bfloat16 sA[128][40];
  __shared__ __nv_bfloat16 sB[128][40];
  __shared__ float rmx[2][128], rmn[2][128], rs[2][128], rq[2][128];
  int t = threadIdx.x, lane = t&31, wid = t>>5;
  int wm = wid>>2, wn = wid&3;
  int rb = blockIdx.x*128, ob = blockIdx.y*128;
  int b = rb>>11;
  float acc[4][4][4];
  #pragma unroll
  for (int i=0;i<4;i++)
    #pragma unroll
    for (int j=0;j<4;j++)
      #pragma unroll
      for (int e=0;e<4;e++) acc[i][j][e]=0.f;

  // addressing for global->reg prefetch (2 uint4 per thread per chunk)
  int s0 = t*2, s1 = t*2+1;
  int row0 = s0>>2, seg0 = (s0&3)*8;
  int row1 = s1>>2, seg1 = (s1&3)*8;
  uint4 pA0, pA1, pB0, pB1;
  pA0 = *(const uint4*)&g_A2[(size_t)(rb+row0)*576 + seg0];
  pA1 = *(const uint4*)&g_A2[(size_t)(rb+row1)*576 + seg1];
  pB0 = *(const uint4*)&g_B2[(size_t)(ob+row0)*576 + seg0];
  pB1 = *(const uint4*)&g_B2[(size_t)(ob+row1)*576 + seg1];

  for (int kc=0; kc<18; kc++){
    __syncthreads();                 // consumers of previous smem done
    *(uint4*)&sA[row0][seg0] = pA0;
    *(uint4*)&sA[row1][seg1] = pA1;
    *(uint4*)&sB[row0][seg0] = pB0;
    *(uint4*)&sB[row1][seg1] = pB1;
    __syncthreads();
    if (kc < 17){
      int off = (kc+1)*32;
      pA0 = *(const uint4*)&g_A2[(size_t)(rb+row0)*576 + off + seg0];
      pA1 = *(const uint4*)&g_A2[(size_t)(rb+row1)*576 + off + seg1];
      pB0 = *(const uint4*)&g_B2[(size_t)(ob+row0)*576 + off + seg0];
      pB1 = *(const uint4*)&g_B2[(size_t)(ob+row1)*576 + off + seg1];
    }
    #pragma unroll
    for (int ks=0; ks<2; ks++){
      unsigned af[4][4];
      #pragma unroll
      for (int i=0;i<4;i++){
        int row = wm*64 + i*16 + (lane & 15);
        int col = ks*16 + (lane>>4)*8;
        unsigned addr = smem_u32(&sA[row][col]);
        asm volatile("ldmatrix.sync.aligned.m8n8.x4.shared.b16 {%0,%1,%2,%3}, [%4];"
          : "=r"(af[i][0]),"=r"(af[i][1]),"=r"(af[i][2]),"=r"(af[i][3]) : "r"(addr));
      }
      unsigned bfm[4][2];
      #pragma unroll
      for (int j=0;j<4;j++){
        int l16 = lane & 15;
        int row = wn*32 + j*8 + (l16 & 7);
        int col = ks*16 + (l16>>3)*8;
        unsigned addr = smem_u32(&sB[row][col]);
        asm volatile("ldmatrix.sync.aligned.m8n8.x2.shared.b16 {%0,%1}, [%2];"
          : "=r"(bfm[j][0]),"=r"(bfm[j][1]) : "r"(addr));
      }
      #pragma unroll
      for (int i=0;i<4;i++)
        #pragma unroll
        for (int j=0;j<4;j++){
          asm volatile(
            "mma.sync.aligned.m16n8k16.row.col.f32.bf16.bf16.f32 "
            "{%0,%1,%2,%3}, {%4,%5,%6,%7}, {%8,%9}, {%0,%1,%2,%3};"
            : "+f"(acc[i][j][0]),"+f"(acc[i][j][1]),"+f"(acc[i][j][2]),"+f"(acc[i][j][3])
            : "r"(af[i][0]),"r"(af[i][1]),"r"(af[i][2]),"r"(af[i][3]),
              "r"(bfm[j][0]),"r"(bfm[j][1]));
        }
    }
  }
  // ---- fused stats epilogue ----
  #pragma unroll
  for (int j=0;j<4;j++){
    #pragma unroll
    for (int e=0;e<2;e++){
      float v0 = acc[0][j][e], v1 = acc[0][j][e+2];
      float mx = fmaxf(v0,v1), mn = fminf(v0,v1);
      float s = v0+v1, q = v0*v0+v1*v1;
      #pragma unroll
      for (int i=1;i<4;i++){
        v0 = acc[i][j][e]; v1 = acc[i][j][e+2];
        mx = fmaxf(mx, fmaxf(v0,v1));
        mn = fminf(mn, fminf(v0,v1));
        s += v0+v1; q += v0*v0+v1*v1;
      }
      #pragma unroll
      for (int off=4; off<32; off<<=1){
        mx = fmaxf(mx, __shfl_xor_sync(0xffffffffu, mx, off));
        mn = fminf(mn, __shfl_xor_sync(0xffffffffu, mn, off));
        s += __shfl_xor_sync(0xffffffffu, s, off);
        q += __shfl_xor_sync(0xffffffffu, q, off);
      }
      if (lane < 4){
        int col = wn*32 + j*8 + lane*2 + e;
        rmx[wm][col]=mx; rmn[wm][col]=mn; rs[wm][col]=s; rq[wm][col]=q;
      }
    }
  }
  __syncthreads();
  if (t < 128){
    float mx = fmaxf(rmx[0][t], rmx[1][t]);
    float mn = fminf(rmn[0][t], rmn[1][t]);
    float s  = rs[0][t] + rs[1][t];
    float q  = rq[0][t] + rq[1][t];
    atomicMax(&g_fmaxe[b*OUTC + ob + t], encf(mx));
    atomicMin(&g_fmine[b*OUTC + ob + t], encf(mn));
    atomicAdd(&g_s1f[ob + t], s);
    atomicAdd(&g_s2f[ob + t], q);
  }
}

// -------- final BN + lrelu + pick max/min ----------------------------------
__global__ void k_fout(const float* __restrict__ gf, const float* __restrict__ bf,
                       float* __restrict__ out){
  int i = blockIdx.x*256 + threadIdx.x;   // 0..16383
  int o = i & (OUTC-1);
  const float cnt = (float)NPTS;
  float mean = g_s1f[o]/cnt;
  float var  = g_s2f[o]/cnt - mean*mean;
  float scale = rsqrtf(var + EPSF) * gf[o];
  float shift = bf[o] - mean*scale;
  float h = (scale>=0.f)? decf(g_fmaxe[i]) : decf(g_fmine[i]);
  float y = h*scale + shift;
  out[i] = (y>=0.f)? y : 0.2f*y;
}

extern "C" void kernel_launch(void* const* d_in, const int* in_sizes, int n_in,
                              void* d_out, int out_size){
  const float* x   = (const float*)d_in[0];
  const float* W[3]  = {(const float*)d_in[1],(const float*)d_in[4],(const float*)d_in[7]};
  const float* G[3]  = {(const float*)d_in[2],(const float*)d_in[5],(const float*)d_in[8]};
  const float* Bv[3] = {(const float*)d_in[3],(const float*)d_in[6],(const float*)d_in[9]};
  const float* Wf = (const float*)d_in[10];
  const float* gf = (const float*)d_in[11];
  const float* bf = (const float*)d_in[12];
  float* out = (float*)d_out;

  k_init<<<64,256>>>();
  k_xx0<<<NPTS/4,256>>>(x);
  k_cvtB<<<(OUTC*CATC)/256,256>>>(Wf);
  for (int l=0;l<3;l++){
    int useCat = (l>0);
    int catOff = useCat ? (l-1)*64 : 0;
    int ldf    = useCat ? CATC : CC;
    k_dist <<<dim3(136, 1, BB),256>>>(x, useCat, catOff, ldf);
    k_topk <<<NPTS/8,256>>>();
    k_pq   <<<NPTS/64,256>>>(x, useCat, catOff, ldf, W[l]);
    k_gather<<<NPTS/64,256>>>(l);
    k_efinal<<<NPTS/4,256>>>(l, G[l], Bv[l], l*64);
  }
  k_fgemm<<<dim3(NPTS/128, OUTC/128),256>>>();
  k_fout <<<BB*OUTC/256,256>>>(gf, bf, out);
}